// round 2
// baseline (speedup 1.0000x reference)
#include <cuda_runtime.h>
#include <math.h>
#include <stdint.h>

// ---------------------------------------------------------------------------
// Problem constants
//   B=4, S=4096, HID=2048, H=16, G=4, D=128, KV=512, M = B*S = 16384
// ---------------------------------------------------------------------------
#define M_ROWS 16384
#define HID    2048
#define KVDIM  512

// Scratch (allocation-free rule: __device__ globals)
__device__ __align__(128) float g_q[(size_t)M_ROWS * HID];
__device__ __align__(128) float g_k[(size_t)M_ROWS * KVDIM];
__device__ __align__(128) float g_v[(size_t)M_ROWS * KVDIM];
__device__ __align__(128) float g_attn[(size_t)M_ROWS * HID];

// ---------------------------------------------------------------------------
// GEMM: C[M,N] = A[M,K] @ B[K,N] + bias[N]   (all row-major, fp32 in/out,
// tf32 tensor-core compute with fp32 accumulation)
// Tiles: BM=128, BN=128, BK=32. 256 threads = 8 warps in a 4x2 warp grid,
// each warp owns a 32x64 tile = 2x8 m16n8k8 MMAs.
// ---------------------------------------------------------------------------
#define BM 128
#define BN 128
#define BKK 32
#define ASTR (BKK + 4)   // 36 floats  (bank-conflict-free fragment loads)
#define BSTR (BN + 4)    // 132 floats

__device__ __forceinline__ void cp_async16(void* smem, const void* gmem) {
    unsigned saddr = (unsigned)__cvta_generic_to_shared(smem);
    asm volatile("cp.async.cg.shared.global [%0], [%1], 16;\n" :: "r"(saddr), "l"(gmem));
}
__device__ __forceinline__ void cp_commit() {
    asm volatile("cp.async.commit_group;\n");
}
template <int N>
__device__ __forceinline__ void cp_wait() {
    asm volatile("cp.async.wait_group %0;\n" :: "n"(N));
}
__device__ __forceinline__ unsigned f2tf32(float x) {
    unsigned r;
    asm("cvt.rna.tf32.f32 %0, %1;" : "=r"(r) : "f"(x));
    return r;
}
__device__ __forceinline__ void mma_tf32(float c[4],
                                         unsigned a0, unsigned a1, unsigned a2, unsigned a3,
                                         unsigned b0, unsigned b1) {
    asm volatile(
        "mma.sync.aligned.m16n8k8.row.col.f32.tf32.tf32.f32 "
        "{%0,%1,%2,%3}, {%4,%5,%6,%7}, {%8,%9}, {%0,%1,%2,%3};\n"
        : "+f"(c[0]), "+f"(c[1]), "+f"(c[2]), "+f"(c[3])
        : "r"(a0), "r"(a1), "r"(a2), "r"(a3), "r"(b0), "r"(b1));
}

__global__ void __launch_bounds__(256, 1)
gemm_tf32(const float* __restrict__ A, const float* __restrict__ Bm,
          const float* __restrict__ bias, float* __restrict__ C,
          int M, int N, int K) {
    extern __shared__ float smem[];
    float* As = smem;                       // 2 * 128 * 36
    float* Bs = smem + 2 * BM * ASTR;       // 2 * 32 * 132

    const int tid  = threadIdx.x;
    const int warp = tid >> 5;
    const int lane = tid & 31;
    const int wm = warp >> 1;       // 0..3 -> warp row (32 rows each)
    const int wn = warp & 1;        // 0..1 -> warp col (64 cols each)
    const int g   = lane >> 2;      // groupID 0..7
    const int tig = lane & 3;       // thread-in-group 0..3

    const int bm = blockIdx.y * BM;
    const int bn = blockIdx.x * BN;

    // global->smem load mapping
    const int arow  = tid >> 3;          // 0..31 (x4 iters of +32)
    const int acol4 = (tid & 7) * 4;     // float idx, 16B aligned
    const int brow  = tid >> 5;          // 0..7  (x4 iters of +8)
    const int bcol4 = (tid & 31) * 4;

    const int KT = K / BKK;

    float acc[2][8][4];
#pragma unroll
    for (int i = 0; i < 2; i++)
#pragma unroll
        for (int j = 0; j < 8; j++)
#pragma unroll
            for (int c = 0; c < 4; c++) acc[i][j][c] = 0.f;

    auto load_tile = [&](int kt, int buf) {
        const float* Ag = A + (size_t)bm * K + (size_t)kt * BKK;
        float* Asb = As + buf * BM * ASTR;
#pragma unroll
        for (int i = 0; i < 4; i++) {
            int r = arow + 32 * i;
            cp_async16(&Asb[r * ASTR + acol4], &Ag[(size_t)r * K + acol4]);
        }
        const float* Bg = Bm + (size_t)(kt * BKK) * N + bn;
        float* Bsb = Bs + buf * BKK * BSTR;
#pragma unroll
        for (int i = 0; i < 4; i++) {
            int r = brow + 8 * i;
            cp_async16(&Bsb[r * BSTR + bcol4], &Bg[(size_t)r * N + bcol4]);
        }
        cp_commit();
    };

    load_tile(0, 0);
    int buf = 0;
    for (int kt = 0; kt < KT; ++kt) {
        cp_wait<0>();
        __syncthreads();   // tile kt visible to all; prev compute finished
        if (kt + 1 < KT) load_tile(kt + 1, buf ^ 1);   // overlaps with compute

        const float* Asb = As + buf * BM * ASTR;
        const float* Bsb = Bs + buf * BKK * BSTR;
#pragma unroll
        for (int ks = 0; ks < 4; ++ks) {
            const int k0 = ks * 8;
            unsigned a[2][4], b[8][2];
#pragma unroll
            for (int mi = 0; mi < 2; ++mi) {
                const int r0 = wm * 32 + mi * 16;
                a[mi][0] = f2tf32(Asb[(r0 + g)     * ASTR + k0 + tig]);
                a[mi][1] = f2tf32(Asb[(r0 + g + 8) * ASTR + k0 + tig]);
                a[mi][2] = f2tf32(Asb[(r0 + g)     * ASTR + k0 + tig + 4]);
                a[mi][3] = f2tf32(Asb[(r0 + g + 8) * ASTR + k0 + tig + 4]);
            }
#pragma unroll
            for (int ni = 0; ni < 8; ++ni) {
                const int c0 = wn * 64 + ni * 8 + g;
                b[ni][0] = f2tf32(Bsb[(k0 + tig)     * BSTR + c0]);
                b[ni][1] = f2tf32(Bsb[(k0 + tig + 4) * BSTR + c0]);
            }
#pragma unroll
            for (int mi = 0; mi < 2; mi++)
#pragma unroll
                for (int ni = 0; ni < 8; ni++)
                    mma_tf32(acc[mi][ni], a[mi][0], a[mi][1], a[mi][2], a[mi][3],
                             b[ni][0], b[ni][1]);
        }
        buf ^= 1;
        __syncthreads();   // all reads of this buffer done before reuse
    }

    // epilogue: + bias, fp32 out
#pragma unroll
    for (int mi = 0; mi < 2; mi++) {
#pragma unroll
        for (int ni = 0; ni < 8; ni++) {
            const int row = bm + wm * 32 + mi * 16 + g;
            const int col = bn + wn * 64 + ni * 8 + tig * 2;
            const float bv0 = bias[col], bv1 = bias[col + 1];
            C[(size_t)row * N + col]         = acc[mi][ni][0] + bv0;
            C[(size_t)row * N + col + 1]     = acc[mi][ni][1] + bv1;
            C[(size_t)(row + 8) * N + col]     = acc[mi][ni][2] + bv0;
            C[(size_t)(row + 8) * N + col + 1] = acc[mi][ni][3] + bv1;
        }
    }
}

// ---------------------------------------------------------------------------
// Attention: per (b,s) position, scores over G=4 groups at the SAME position.
// 1 CTA (256 thr) per position. Warp w handles heads 2w, 2w+1.
// ---------------------------------------------------------------------------
__global__ void __launch_bounds__(256)
attn_kernel(const float* __restrict__ Q, const float* __restrict__ Kp,
            const float* __restrict__ Vp, float* __restrict__ Out) {
    const int m = blockIdx.x;
    __shared__ float ks[512], vs[512];
    const int tid = threadIdx.x;
    const float* kr = Kp + (size_t)m * KVDIM;
    const float* vr = Vp + (size_t)m * KVDIM;
    for (int i = tid; i < 512; i += 256) { ks[i] = kr[i]; vs[i] = vr[i]; }
    __syncthreads();

    const int warp = tid >> 5, lane = tid & 31;
    const float* qr   = Q   + (size_t)m * HID;
    float*       orow = Out + (size_t)m * HID;

#pragma unroll
    for (int hh = 0; hh < 2; ++hh) {
        const int h = warp * 2 + hh;
        float qv[4];
#pragma unroll
        for (int j = 0; j < 4; j++) qv[j] = qr[h * 128 + lane + 32 * j];
        float s[4];
#pragma unroll
        for (int gi = 0; gi < 4; ++gi) {
            float p = 0.f;
#pragma unroll
            for (int j = 0; j < 4; j++) p += qv[j] * ks[gi * 128 + lane + 32 * j];
#pragma unroll
            for (int off = 16; off > 0; off >>= 1)
                p += __shfl_xor_sync(0xffffffffu, p, off);
            s[gi] = p * 0.088388347648318447f;   // 1/sqrt(128)
        }
        const float mx = fmaxf(fmaxf(s[0], s[1]), fmaxf(s[2], s[3]));
        float e0 = __expf(s[0] - mx), e1 = __expf(s[1] - mx);
        float e2 = __expf(s[2] - mx), e3 = __expf(s[3] - mx);
        const float inv = 1.f / (e0 + e1 + e2 + e3);
        e0 *= inv; e1 *= inv; e2 *= inv; e3 *= inv;
#pragma unroll
        for (int j = 0; j < 4; j++) {
            const int d = lane + 32 * j;
            orow[h * 128 + d] = e0 * vs[d] + e1 * vs[128 + d] +
                                e2 * vs[256 + d] + e3 * vs[384 + d];
        }
    }
}

// ---------------------------------------------------------------------------
// Launch
// inputs: hidden_states, Wq, bq, Wk, bk, Wv, bv, Wo, bo
// ---------------------------------------------------------------------------
extern "C" void kernel_launch(void* const* d_in, const int* in_sizes, int n_in,
                              void* d_out, int out_size) {
    const float* x  = (const float*)d_in[0];
    const float* Wq = (const float*)d_in[1];
    const float* bq = (const float*)d_in[2];
    const float* Wk = (const float*)d_in[3];
    const float* bk = (const float*)d_in[4];
    const float* Wv = (const float*)d_in[5];
    const float* bv = (const float*)d_in[6];
    const float* Wo = (const float*)d_in[7];
    const float* bo = (const float*)d_in[8];
    float* out = (float*)d_out;

    float *q, *k, *v, *attn;
    cudaGetSymbolAddress((void**)&q, g_q);
    cudaGetSymbolAddress((void**)&k, g_k);
    cudaGetSymbolAddress((void**)&v, g_v);
    cudaGetSymbolAddress((void**)&attn, g_attn);

    const size_t smem = (size_t)(2 * BM * ASTR + 2 * BKK * BSTR) * sizeof(float); // 70656 B
    cudaFuncSetAttribute(gemm_tf32, cudaFuncAttributeMaxDynamicSharedMemorySize, (int)smem);

    dim3 blk(256);
    // Q = x @ Wq + bq   [16384, 2048]
    gemm_tf32<<<dim3(HID / BN, M_ROWS / BM), blk, smem>>>(x, Wq, bq, q, M_ROWS, HID, HID);
    // K = x @ Wk + bk   [16384, 512]
    gemm_tf32<<<dim3(KVDIM / BN, M_ROWS / BM), blk, smem>>>(x, Wk, bk, k, M_ROWS, KVDIM, HID);
    // V = x @ Wv + bv   [16384, 512]
    gemm_tf32<<<dim3(KVDIM / BN, M_ROWS / BM), blk, smem>>>(x, Wv, bv, v, M_ROWS, KVDIM, HID);
    // attention over groups at same position
    attn_kernel<<<M_ROWS, 256>>>(q, k, v, attn);
    // out = attn @ Wo + bo
    gemm_tf32<<<dim3(HID / BN, M_ROWS / BM), blk, smem>>>(attn, Wo, bo, out, M_ROWS, HID, HID);
}

// round 9
// speedup vs baseline: 1.1962x; 1.1962x over previous
#include <cuda_runtime.h>
#include <math.h>
#include <stdint.h>

// ---------------------------------------------------------------------------
// B=4, S=4096, HID=2048, H=16, G=4, D=128, KV=512, M = B*S = 16384, K = 2048
// ---------------------------------------------------------------------------
#define M_ROWS 16384
#define KDIM   2048
#define HID    2048
#define KVDIM  512

// Scratch (__device__ globals: allocation-free rule)
__device__ __align__(128) float g_q[(size_t)M_ROWS * HID];
__device__ __align__(128) float g_k[(size_t)M_ROWS * KVDIM];
__device__ __align__(128) float g_v[(size_t)M_ROWS * KVDIM];
__device__ __align__(128) float g_attn[(size_t)M_ROWS * HID];
__device__ __align__(128) float g_xr[(size_t)M_ROWS * HID];
__device__ __align__(128) float g_wqt[(size_t)HID * KDIM];
__device__ __align__(128) float g_wkt[(size_t)KVDIM * KDIM];
__device__ __align__(128) float g_wvt[(size_t)KVDIM * KDIM];
__device__ __align__(128) float g_wot[(size_t)HID * KDIM];

// ---------------------------------------------------------------------------
// PTX helpers (base sm_103 ISA only — no 'a'-suffix features)
// ---------------------------------------------------------------------------
__device__ __forceinline__ uint32_t smem_u32(const void* p) {
    uint32_t a;
    asm("{ .reg .u64 t; cvta.to.shared.u64 t, %1; cvt.u32.u64 %0, t; }" : "=r"(a) : "l"(p));
    return a;
}
__device__ __forceinline__ unsigned f2tf32(float x) {
    unsigned r;
    asm("cvt.rna.tf32.f32 %0, %1;" : "=r"(r) : "f"(x));
    return r;
}
__device__ __forceinline__ void cp_async16(uint32_t saddr, const void* gmem) {
    asm volatile("cp.async.cg.shared.global [%0], [%1], 16;\n" :: "r"(saddr), "l"(gmem));
}
__device__ __forceinline__ void cp_commit() { asm volatile("cp.async.commit_group;\n"); }
template <int N>
__device__ __forceinline__ void cp_wait() { asm volatile("cp.async.wait_group %0;\n" :: "n"(N)); }

__device__ __forceinline__ void ldsm4(uint32_t r[4], uint32_t addr) {
    asm volatile("ldmatrix.sync.aligned.m8n8.x4.shared.b16 {%0,%1,%2,%3}, [%4];"
                 : "=r"(r[0]), "=r"(r[1]), "=r"(r[2]), "=r"(r[3]) : "r"(addr));
}
__device__ __forceinline__ void mma_tf32(float c[4],
                                         const uint32_t a[4], uint32_t b0, uint32_t b1) {
    asm volatile(
        "mma.sync.aligned.m16n8k8.row.col.f32.tf32.tf32.f32 "
        "{%0,%1,%2,%3}, {%4,%5,%6,%7}, {%8,%9}, {%0,%1,%2,%3};\n"
        : "+f"(c[0]), "+f"(c[1]), "+f"(c[2]), "+f"(c[3])
        : "r"(a[0]), "r"(a[1]), "r"(a[2]), "r"(a[3]), "r"(b0), "r"(b1));
}

// ---------------------------------------------------------------------------
// GEMM: C[M,N] = A[M,K] @ Bt[N,K]^T + bias     (A,Bt pre-rounded to tf32-rna)
// CTA tile 128x128, BK=32 floats. 8 warps (4x2), warp tile 32x64.
// 4-stage cp.async ring, XOR-swizzled smem, ldmatrix fragment loads.
// ---------------------------------------------------------------------------
#define NSTAGE 4
#define KT_CNT 64                       // K / 32
#define STG_A  16384                    // 128 rows * 128 B
#define STG_B  16384
#define SM_B_OFF (NSTAGE * STG_A)
#define SMEM_BYTES (NSTAGE * (STG_A + STG_B))   // 131072

__global__ void __launch_bounds__(256, 1)
gemm_tc(const float* __restrict__ A, const float* __restrict__ Bt,
        const float* __restrict__ bias, float* __restrict__ C, int N) {
    extern __shared__ char smem[];
    const uint32_t sb = smem_u32(smem);
    const int tid = threadIdx.x, warp = tid >> 5, lane = tid & 31;
    const int wm = warp >> 1, wn = warp & 1;
    const int bm = blockIdx.y * 128;
    const int bn = blockIdx.x * 128;

    // ---- per-lane ldmatrix address bases (swizzle folded; bits disjoint) ----
    uint32_t aBase[2], aXk[2], bBase[4], bXk[4];
    {
        const int f = lane >> 3;
        // A: frag f -> rows ((f&1)*8 + l%8), k-chunk (f>>1)
        const int rinA = ((f & 1) << 3) | (lane & 7);
        const int cfA = f >> 1;
#pragma unroll
        for (int mi = 0; mi < 2; mi++) {
            const int row = wm * 32 + mi * 16 + rinA;
            const int rm = row & 7;
            aBase[mi] = (uint32_t)(row * 128 + ((cfA ^ (rm & 1)) << 4));
            aXk[mi]   = (uint32_t)((rm & 6) << 4);
        }
        // B: frag f -> n-rows ((f>>1)*8 + l%8), k-chunk (f&1)
        const int rinB = ((f >> 1) << 3) | (lane & 7);
        const int cfB = f & 1;
#pragma unroll
        for (int p = 0; p < 4; p++) {
            const int nrow = wn * 64 + p * 16 + rinB;
            const int rm = nrow & 7;
            bBase[p] = (uint32_t)(nrow * 128 + ((cfB ^ (rm & 1)) << 4));
            bXk[p]   = (uint32_t)((rm & 6) << 4);
        }
    }

    float acc[2][8][4];
#pragma unroll
    for (int i = 0; i < 2; i++)
#pragma unroll
        for (int j = 0; j < 8; j++)
#pragma unroll
            for (int c = 0; c < 4; c++) acc[i][j][c] = 0.f;

    // gmem->smem: 16B chunks, swizzled chunk = c ^ (row&7)
    auto load_stage = [&](int kt, int buf) {
#pragma unroll
        for (int i = 0; i < 4; i++) {
            const int idx = tid + i * 256;
            const int row = idx >> 3, c = idx & 7;
            const uint32_t sw = (uint32_t)(row * 128 + ((c ^ (row & 7)) << 4));
            cp_async16(sb + buf * STG_A + sw,
                       A + (size_t)(bm + row) * KDIM + kt * 32 + c * 4);
        }
#pragma unroll
        for (int i = 0; i < 4; i++) {
            const int idx = tid + i * 256;
            const int row = idx >> 3, c = idx & 7;
            const uint32_t sw = (uint32_t)(row * 128 + ((c ^ (row & 7)) << 4));
            cp_async16(sb + SM_B_OFF + buf * STG_B + sw,
                       Bt + (size_t)(bn + row) * KDIM + kt * 32 + c * 4);
        }
        cp_commit();
    };

#pragma unroll
    for (int s = 0; s < NSTAGE; s++) load_stage(s, s);

    for (int kt = 0; kt < KT_CNT; kt++) {
        if (kt < KT_CNT - 2)       cp_wait<2>();
        else if (kt == KT_CNT - 2) cp_wait<1>();
        else                       cp_wait<0>();
        __syncthreads();
        if (kt >= 1 && kt + 3 < KT_CNT) load_stage(kt + 3, (kt + 3) & 3);

        const int buf = kt & 3;
        const uint32_t aS = sb + buf * STG_A;
        const uint32_t bS = sb + SM_B_OFF + buf * STG_B;
#pragma unroll
        for (int ks = 0; ks < 4; ks++) {
            uint32_t a[2][4];
#pragma unroll
            for (int mi = 0; mi < 2; mi++)
                ldsm4(a[mi], aS + (aBase[mi] | ((32u * ks) ^ aXk[mi])));
            uint32_t b[4][4];
#pragma unroll
            for (int p = 0; p < 4; p++)
                ldsm4(b[p], bS + (bBase[p] | ((32u * ks) ^ bXk[p])));
#pragma unroll
            for (int mi = 0; mi < 2; mi++)
#pragma unroll
                for (int p = 0; p < 4; p++) {
                    mma_tf32(acc[mi][2 * p],     a[mi], b[p][0], b[p][1]);
                    mma_tf32(acc[mi][2 * p + 1], a[mi], b[p][2], b[p][3]);
                }
        }
    }

    // epilogue: + bias, fp32 out
    const int g = lane >> 2, tig = lane & 3;
#pragma unroll
    for (int mi = 0; mi < 2; mi++) {
#pragma unroll
        for (int ni = 0; ni < 8; ni++) {
            const int row = bm + wm * 32 + mi * 16 + g;
            const int col = bn + wn * 64 + ni * 8 + tig * 2;
            const float bv0 = bias[col], bv1 = bias[col + 1];
            float2 o0 = {acc[mi][ni][0] + bv0, acc[mi][ni][1] + bv1};
            float2 o1 = {acc[mi][ni][2] + bv0, acc[mi][ni][3] + bv1};
            *(float2*)(C + (size_t)row * N + col)       = o0;
            *(float2*)(C + (size_t)(row + 8) * N + col) = o1;
        }
    }
}

// ---------------------------------------------------------------------------
// Weight transpose + tf32-rna rounding: Wt[n,k] = rna(W[k,n]); W is [K,N]
// ---------------------------------------------------------------------------
__global__ void __launch_bounds__(256)
transpose_round(const float* __restrict__ W, float* __restrict__ Wt, int K, int N) {
    __shared__ float t[32][33];
    const int k0 = blockIdx.x * 32, n0 = blockIdx.y * 32;
    const int tx = threadIdx.x & 31, ty = threadIdx.x >> 5;   // ty 0..7
#pragma unroll
    for (int i = 0; i < 32; i += 8)
        t[ty + i][tx] = W[(size_t)(k0 + ty + i) * N + n0 + tx];
    __syncthreads();
#pragma unroll
    for (int i = 0; i < 32; i += 8)
        Wt[(size_t)(n0 + ty + i) * K + k0 + tx] = __uint_as_float(f2tf32(t[tx][ty + i]));
}

// x -> rna-rounded copy (so raw bits fed to tf32 MMA == rna-rounded operand)
__global__ void __launch_bounds__(256)
round4(const float4* __restrict__ in, float4* __restrict__ out, int n4) {
    for (int i = blockIdx.x * 256 + threadIdx.x; i < n4; i += gridDim.x * 256) {
        float4 v = in[i];
        v.x = __uint_as_float(f2tf32(v.x));
        v.y = __uint_as_float(f2tf32(v.y));
        v.z = __uint_as_float(f2tf32(v.z));
        v.w = __uint_as_float(f2tf32(v.w));
        out[i] = v;
    }
}

// ---------------------------------------------------------------------------
// Attention over G=4 groups at same position; output rna-rounded (feeds the
// tf32 O-projection as the A operand).
// ---------------------------------------------------------------------------
__global__ void __launch_bounds__(256)
attn_kernel(const float* __restrict__ Q, const float* __restrict__ Kp,
            const float* __restrict__ Vp, float* __restrict__ Out) {
    const int m = blockIdx.x;
    __shared__ float ks[512], vs[512];
    const int tid = threadIdx.x;
    const float* kr = Kp + (size_t)m * KVDIM;
    const float* vr = Vp + (size_t)m * KVDIM;
    for (int i = tid; i < 512; i += 256) { ks[i] = kr[i]; vs[i] = vr[i]; }
    __syncthreads();

    const int warp = tid >> 5, lane = tid & 31;
    const float* qr   = Q   + (size_t)m * HID;
    float*       orow = Out + (size_t)m * HID;

#pragma unroll
    for (int hh = 0; hh < 2; ++hh) {
        const int h = warp * 2 + hh;
        float qv[4];
#pragma unroll
        for (int j = 0; j < 4; j++) qv[j] = qr[h * 128 + lane + 32 * j];
        float s[4];
#pragma unroll
        for (int gi = 0; gi < 4; ++gi) {
            float p = 0.f;
#pragma unroll
            for (int j = 0; j < 4; j++) p += qv[j] * ks[gi * 128 + lane + 32 * j];
#pragma unroll
            for (int off = 16; off > 0; off >>= 1)
                p += __shfl_xor_sync(0xffffffffu, p, off);
            s[gi] = p * 0.088388347648318447f;   // 1/sqrt(128)
        }
        const float mx = fmaxf(fmaxf(s[0], s[1]), fmaxf(s[2], s[3]));
        float e0 = __expf(s[0] - mx), e1 = __expf(s[1] - mx);
        float e2 = __expf(s[2] - mx), e3 = __expf(s[3] - mx);
        const float inv = 1.f / (e0 + e1 + e2 + e3);
        e0 *= inv; e1 *= inv; e2 *= inv; e3 *= inv;
#pragma unroll
        for (int j = 0; j < 4; j++) {
            const int d = lane + 32 * j;
            const float o = e0 * vs[d] + e1 * vs[128 + d] +
                            e2 * vs[256 + d] + e3 * vs[384 + d];
            orow[h * 128 + d] = __uint_as_float(f2tf32(o));
        }
    }
}

// ---------------------------------------------------------------------------
// Launch: hidden_states, Wq, bq, Wk, bk, Wv, bv, Wo, bo
// ---------------------------------------------------------------------------
extern "C" void kernel_launch(void* const* d_in, const int* in_sizes, int n_in,
                              void* d_out, int out_size) {
    const float* x  = (const float*)d_in[0];
    const float* Wq = (const float*)d_in[1];
    const float* bq = (const float*)d_in[2];
    const float* Wk = (const float*)d_in[3];
    const float* bk = (const float*)d_in[4];
    const float* Wv = (const float*)d_in[5];
    const float* bv = (const float*)d_in[6];
    const float* Wo = (const float*)d_in[7];
    const float* bo = (const float*)d_in[8];
    float* out = (float*)d_out;

    float *q, *k, *v, *attn, *xr, *wqt, *wkt, *wvt, *wot;
    cudaGetSymbolAddress((void**)&q,    g_q);
    cudaGetSymbolAddress((void**)&k,    g_k);
    cudaGetSymbolAddress((void**)&v,    g_v);
    cudaGetSymbolAddress((void**)&attn, g_attn);
    cudaGetSymbolAddress((void**)&xr,   g_xr);
    cudaGetSymbolAddress((void**)&wqt,  g_wqt);
    cudaGetSymbolAddress((void**)&wkt,  g_wkt);
    cudaGetSymbolAddress((void**)&wvt,  g_wvt);
    cudaGetSymbolAddress((void**)&wot,  g_wot);

    cudaFuncSetAttribute(gemm_tc, cudaFuncAttributeMaxDynamicSharedMemorySize, SMEM_BYTES);

    // Prep: transpose+round weights, round activations
    transpose_round<<<dim3(KDIM / 32, HID / 32),   256>>>(Wq, wqt, KDIM, HID);
    transpose_round<<<dim3(KDIM / 32, KVDIM / 32), 256>>>(Wk, wkt, KDIM, KVDIM);
    transpose_round<<<dim3(KDIM / 32, KVDIM / 32), 256>>>(Wv, wvt, KDIM, KVDIM);
    transpose_round<<<dim3(KDIM / 32, HID / 32),   256>>>(Wo, wot, KDIM, HID);
    round4<<<8192, 256>>>((const float4*)x, (float4*)xr, (M_ROWS * HID) / 4);

    // Projections (tf32 tensor cores, ldmatrix path)
    gemm_tc<<<dim3(HID / 128,   M_ROWS / 128), 256, SMEM_BYTES>>>(xr, wqt, bq, q, HID);
    gemm_tc<<<dim3(KVDIM / 128, M_ROWS / 128), 256, SMEM_BYTES>>>(xr, wkt, bk, k, KVDIM);
    gemm_tc<<<dim3(KVDIM / 128, M_ROWS / 128), 256, SMEM_BYTES>>>(xr, wvt, bv, v, KVDIM);

    // Attention (writes rna-rounded A operand for O-projection)
    attn_kernel<<<M_ROWS, 256>>>(q, k, v, attn);

    // Output projection
    gemm_tc<<<dim3(HID / 128, M_ROWS / 128), 256, SMEM_BYTES>>>(attn, wot, bo, out, HID);
}